// round 5
// baseline (speedup 1.0000x reference)
#include <cuda_runtime.h>
#include <math.h>

#define MAXROWS 4096
typedef unsigned long long ull;

// Precomputed pair-group coefficients, plain float both sides.
// Layout: [(g*4+p)*N + row], g in [0,8), p in [0,4).
__device__ float g_A[32 * MAXROWS];
__device__ float g_B[32 * MAXROWS];

// Packed f32x2 helpers (Blackwell sm_100+).
#define MUL_F32X2(out, a, b) \
    asm("mul.rn.f32x2 %0, %1, %2;" : "=l"(out) : "l"(a), "l"(b))
#define FMA_F32X2(acc, a, b) \
    asm("fma.rn.f32x2 %0, %1, %2, %0;" : "+l"(acc) : "l"(a), "l"(b))
#define ABS_F32X2(out, a) \
    asm("and.b64 %0, %1, %2;" : "=l"(out) : "l"(a), "l"(0x7FFFFFFF7FFFFFFFULL))
#define DUP_F32X2(out, v) \
    asm("mov.b64 %0, {%1, %1};" : "=l"(out) : "f"(v))

// ---------------------------------------------------------------------------
// Precompute per row r, wire-pair g: (c0*c1, c0*s1, s0*c1, s0*s1).
// Then cos((x0-y0)/2)*cos((x1-y1)/2) = dot4(A[i][g], B[j][g]).
// ---------------------------------------------------------------------------
__global__ void qk_precompute(const float* __restrict__ x,
                              const float* __restrict__ y,
                              int n, int m, int d) {
    int tid = blockIdx.x * blockDim.x + threadIdx.x;
    int total = (n + m) * 8;
    if (tid >= total) return;
    int g = tid & 7;
    int r = tid >> 3;
    const float* src;
    float* dst;
    int N;
    if (r < n) {
        src = x + (size_t)r * d;
        dst = g_A;
        N = n;
    } else {
        r -= n;
        src = y + (size_t)r * d;
        dst = g_B;
        N = m;
    }
    float s0, c0, s1, c1;
    sincosf(0.5f * src[2 * g],     &s0, &c0);
    sincosf(0.5f * src[2 * g + 1], &s1, &c1);
    dst[(g * 4 + 0) * N + r] = c0 * c1;
    dst[(g * 4 + 1) * N + r] = c0 * s1;
    dst[(g * 4 + 2) * N + r] = s0 * c1;
    dst[(g * 4 + 3) * N + r] = s0 * s1;
}

// ---------------------------------------------------------------------------
// Main kernel: CTA tile 32(i) x 128(j), 128 threads, per-thread 4i x 8j,
// f32x2 packed over j. Per g per thread:
//   8 LDS.128 (B) + 4 LDS.128 (A, transposed layout) + 16 ALU DUP + 80 FMA.
// Smem traffic 48 B/output; t kept transient per-ii to hold regs ~100.
// ---------------------------------------------------------------------------
__global__ __launch_bounds__(128, 4)
void qk_prod(float* __restrict__ out, int n, int m) {
    __shared__ float As2[32][36];   // [i_local][slice], stride 36 keeps
                                    // LDS.128 16B-aligned, near-conflict-free
    __shared__ float Bs[32][128];   // [slice][j_local]

    const int i_base = blockIdx.y * 32;
    const int j_base = blockIdx.x * 128;
    const int tid = threadIdx.x;

    // Fill As2 (transposed): 1024 scalar loads, coalesced over rows.
    #pragma unroll
    for (int k = 0; k < 8; k++) {
        int idx = tid + k * 128;
        int slice = idx >> 5;          // 0..31
        int row = idx & 31;            // 0..31
        As2[row][slice] = g_A[(size_t)slice * n + i_base + row];
    }
    // Fill Bs: 1024 float4.
    #pragma unroll
    for (int k = 0; k < 8; k++) {
        int idx = tid + k * 128;
        int slice = idx >> 5;
        int pos = (idx & 31) << 2;
        *(float4*)&Bs[slice][pos] =
            *(const float4*)&g_B[(size_t)slice * m + j_base + pos];
    }
    __syncthreads();

    const int tx = tid & 15;        // j: 16 threads x 8 = 128
    const int ty = tid >> 4;        // i: 8 threads x 4 = 32
    const int i0 = ty * 4;
    const int j0 = tx * 8;

    ull prod[4][4];                 // [ii][jpair]

    // ---- g = 0 (peeled): init prod ----
    {
        ull b[4][4];
        #pragma unroll
        for (int p = 0; p < 4; p++) {
            ulonglong2 v0 = *(const ulonglong2*)&Bs[p][j0];
            ulonglong2 v1 = *(const ulonglong2*)&Bs[p][j0 + 4];
            b[p][0] = v0.x; b[p][1] = v0.y; b[p][2] = v1.x; b[p][3] = v1.y;
        }
        #pragma unroll
        for (int ii = 0; ii < 4; ii++) {
            float4 av = *(const float4*)&As2[i0 + ii][0];
            ull a0, a1, a2, a3;
            DUP_F32X2(a0, av.x); DUP_F32X2(a1, av.y);
            DUP_F32X2(a2, av.z); DUP_F32X2(a3, av.w);
            #pragma unroll
            for (int q = 0; q < 4; q++) {
                ull t;
                MUL_F32X2(t, a0, b[0][q]);
                FMA_F32X2(t, a1, b[1][q]);
                FMA_F32X2(t, a2, b[2][q]);
                FMA_F32X2(t, a3, b[3][q]);
                prod[ii][q] = t;
            }
        }
    }

    // ---- g = 1..7 ----
    #pragma unroll 1
    for (int g = 1; g < 8; g++) {
        ull b[4][4];
        #pragma unroll
        for (int p = 0; p < 4; p++) {
            ulonglong2 v0 = *(const ulonglong2*)&Bs[g * 4 + p][j0];
            ulonglong2 v1 = *(const ulonglong2*)&Bs[g * 4 + p][j0 + 4];
            b[p][0] = v0.x; b[p][1] = v0.y; b[p][2] = v1.x; b[p][3] = v1.y;
        }
        #pragma unroll
        for (int ii = 0; ii < 4; ii++) {
            float4 av = *(const float4*)&As2[i0 + ii][g * 4];
            ull a0, a1, a2, a3;
            DUP_F32X2(a0, av.x); DUP_F32X2(a1, av.y);
            DUP_F32X2(a2, av.z); DUP_F32X2(a3, av.w);
            #pragma unroll
            for (int q = 0; q < 4; q++) {
                ull t;
                MUL_F32X2(t, a0, b[0][q]);
                FMA_F32X2(t, a1, b[1][q]);
                FMA_F32X2(t, a2, b[2][q]);
                FMA_F32X2(t, a3, b[3][q]);
                MUL_F32X2(prod[ii][q], prod[ii][q], t);
            }
        }
    }

    // ---- epilogue: abs + STG.128 (two ulonglong2 per row) ----
    #pragma unroll
    for (int ii = 0; ii < 4; ii++) {
        ull v0, v1, v2, v3;
        ABS_F32X2(v0, prod[ii][0]);
        ABS_F32X2(v1, prod[ii][1]);
        ABS_F32X2(v2, prod[ii][2]);
        ABS_F32X2(v3, prod[ii][3]);
        int row = i_base + i0 + ii;
        ulonglong2* dst = (ulonglong2*)&out[(size_t)row * m + j_base + j0];
        dst[0] = make_ulonglong2(v0, v1);
        dst[1] = make_ulonglong2(v2, v3);
    }
}

// ---------------------------------------------------------------------------
// Generic fallback (shape-robust, slow): one thread per output.
// ---------------------------------------------------------------------------
__global__ void qk_generic(const float* __restrict__ x, const float* __restrict__ y,
                           float* __restrict__ out, int n, int m, int d) {
    long long idx = (long long)blockIdx.x * blockDim.x + threadIdx.x;
    long long total = (long long)n * m;
    if (idx >= total) return;
    int i = (int)(idx / m);
    int j = (int)(idx % m);
    float prod = 1.0f;
    for (int k = 0; k < d; k++)
        prod *= cosf(0.5f * (x[(size_t)i * d + k] - y[(size_t)j * d + k]));
    out[idx] = fabsf(prod);
}

extern "C" void kernel_launch(void* const* d_in, const int* in_sizes, int n_in,
                              void* d_out, int out_size) {
    const float* x = (const float*)d_in[0];
    const float* y = (const float*)d_in[1];
    float* out = (float*)d_out;

    double dd = sqrt((double)in_sizes[0] * (double)in_sizes[1] / (double)out_size);
    int d = (int)(dd + 0.5);
    if (d <= 0) d = 16;
    int n = in_sizes[0] / d;
    int m = in_sizes[1] / d;

    bool fast = (d == 16) && (n % 32 == 0) && (m % 128 == 0) &&
                (n <= MAXROWS) && (m <= MAXROWS) &&
                ((long long)n * d == in_sizes[0]) &&
                ((long long)m * d == in_sizes[1]) &&
                ((long long)n * m == out_size);

    if (fast) {
        int total = (n + m) * 8;
        qk_precompute<<<(total + 255) / 256, 256>>>(x, y, n, m, d);
        dim3 grid(m / 128, n / 32);
        qk_prod<<<grid, 128>>>(out, n, m);
    } else {
        long long total = (long long)n * m;
        int blocks = (int)((total + 255) / 256);
        qk_generic<<<blocks, 256>>>(x, y, out, n, m, d);
    }
}

// round 6
// speedup vs baseline: 1.6042x; 1.6042x over previous
#include <cuda_runtime.h>
#include <math.h>

// ---------------------------------------------------------------------------
// Fused kernel: CTA tile 64(i) x 64(j), 256 threads, 4x4 per thread, scalar
// FFMA. Coefficients (c0c1, c0s1, s0c1, s0s1) per wire-pair are computed
// in-CTA from x,y via MUFU sincos (no precompute kernel, no global scratch).
// out[i,j] = | prod_g dot4(A[i][g], B[j][g]) |  with 8 pair-groups g.
// ---------------------------------------------------------------------------
__global__ __launch_bounds__(256, 5)
void qk_fused(const float* __restrict__ x, const float* __restrict__ y,
              float* __restrict__ out, int n, int m) {
    __shared__ float As[32][64];   // [g*4+p][i_local]
    __shared__ float Bs[32][64];   // [g*4+p][j_local]

    const int i_base = blockIdx.y * 64;
    const int j_base = blockIdx.x * 64;
    const int tid = threadIdx.x;

    // ---- prologue: compute coefficient tiles directly into smem ----
    // 256 tasks: (A/B) x 64 rows x 2 halves. Each task: 8 wires -> 8 sincos,
    // 16 STS. Warp lanes span 16 rows x 2 halves -> <=2-way STS conflicts.
    {
        const int isB  = tid >> 7;          // threads 0-127: A, 128-255: B
        const int row  = (tid >> 1) & 63;
        const int half = tid & 1;           // wires 8*half .. 8*half+7
        const float* src = (isB ? y + (size_t)(j_base + row) * 16
                                : x + (size_t)(i_base + row) * 16) + 8 * half;
        float (*dst)[64] = isB ? Bs : As;
        float4 v0 = *(const float4*)(src);
        float4 v1 = *(const float4*)(src + 4);
        float w[8] = {v0.x, v0.y, v0.z, v0.w, v1.x, v1.y, v1.z, v1.w};
        #pragma unroll
        for (int q = 0; q < 4; q++) {
            int g = 4 * half + q;           // pair-group index
            float s0, c0, s1, c1;
            __sincosf(0.5f * w[2 * q],     &s0, &c0);
            __sincosf(0.5f * w[2 * q + 1], &s1, &c1);
            dst[4 * g + 0][row] = c0 * c1;
            dst[4 * g + 1][row] = c0 * s1;
            dst[4 * g + 2][row] = s0 * c1;
            dst[4 * g + 3][row] = s0 * s1;
        }
    }
    __syncthreads();

    // ---- mainloop: 4x4 outputs per thread, sequential-p (register-lean) ----
    const int tx = tid & 15;        // j: 16 threads x 4 = 64
    const int ty = tid >> 4;        // i: 16 threads x 4 = 64
    const int i0 = ty * 4;
    const int j0 = tx * 4;

    float prod[4][4];

    #pragma unroll 1
    for (int g = 0; g < 8; g++) {
        float t[4][4];
        #pragma unroll
        for (int p = 0; p < 4; p++) {
            float4 av = *(const float4*)&As[g * 4 + p][i0];  // broadcast
            float4 bv = *(const float4*)&Bs[g * 4 + p][j0];  // conflict-free
            float a[4] = {av.x, av.y, av.z, av.w};
            float b[4] = {bv.x, bv.y, bv.z, bv.w};
            if (p == 0) {
                #pragma unroll
                for (int ii = 0; ii < 4; ii++)
                    #pragma unroll
                    for (int jj = 0; jj < 4; jj++)
                        t[ii][jj] = a[ii] * b[jj];
            } else {
                #pragma unroll
                for (int ii = 0; ii < 4; ii++)
                    #pragma unroll
                    for (int jj = 0; jj < 4; jj++)
                        t[ii][jj] = fmaf(a[ii], b[jj], t[ii][jj]);
            }
        }
        if (g == 0) {
            #pragma unroll
            for (int ii = 0; ii < 4; ii++)
                #pragma unroll
                for (int jj = 0; jj < 4; jj++)
                    prod[ii][jj] = t[ii][jj];
        } else {
            #pragma unroll
            for (int ii = 0; ii < 4; ii++)
                #pragma unroll
                for (int jj = 0; jj < 4; jj++)
                    prod[ii][jj] *= t[ii][jj];
        }
    }

    // ---- epilogue: abs + one float4 store per row ----
    #pragma unroll
    for (int ii = 0; ii < 4; ii++) {
        float4 v;
        v.x = fabsf(prod[ii][0]);
        v.y = fabsf(prod[ii][1]);
        v.z = fabsf(prod[ii][2]);
        v.w = fabsf(prod[ii][3]);
        *(float4*)&out[(size_t)(i_base + i0 + ii) * m + (j_base + j0)] = v;
    }
}

// ---------------------------------------------------------------------------
// Generic fallback (shape-robust, slow): one thread per output.
// ---------------------------------------------------------------------------
__global__ void qk_generic(const float* __restrict__ x, const float* __restrict__ y,
                           float* __restrict__ out, int n, int m, int d) {
    long long idx = (long long)blockIdx.x * blockDim.x + threadIdx.x;
    long long total = (long long)n * m;
    if (idx >= total) return;
    int i = (int)(idx / m);
    int j = (int)(idx % m);
    float prod = 1.0f;
    for (int k = 0; k < d; k++)
        prod *= cosf(0.5f * (x[(size_t)i * d + k] - y[(size_t)j * d + k]));
    out[idx] = fabsf(prod);
}

extern "C" void kernel_launch(void* const* d_in, const int* in_sizes, int n_in,
                              void* d_out, int out_size) {
    const float* x = (const float*)d_in[0];
    const float* y = (const float*)d_in[1];
    float* out = (float*)d_out;

    // Recover (n, m, d): in_sizes = {n*d, m*d}, out_size = n*m.
    double dd = sqrt((double)in_sizes[0] * (double)in_sizes[1] / (double)out_size);
    int d = (int)(dd + 0.5);
    if (d <= 0) d = 16;
    int n = in_sizes[0] / d;
    int m = in_sizes[1] / d;

    bool fast = (d == 16) && (n % 64 == 0) && (m % 64 == 0) &&
                ((long long)n * d == in_sizes[0]) &&
                ((long long)m * d == in_sizes[1]) &&
                ((long long)n * m == out_size);

    if (fast) {
        dim3 grid(m / 64, n / 64);
        qk_fused<<<grid, 256>>>(x, y, out, n, m);
    } else {
        long long total = (long long)n * m;
        int blocks = (int)((total + 255) / 256);
        qk_generic<<<blocks, 256>>>(x, y, out, n, m, d);
    }
}